// round 5
// baseline (speedup 1.0000x reference)
#include <cuda_runtime.h>

#define EMB   64
#define NSPH  16
#define KMAX  24
#define MAX_EDGES 131072
#define NBLOCKS 456   // 3 per SM * 152

typedef unsigned long long u64;

__device__ int   g_start[MAX_EDGES];
__device__ int   g_count[MAX_EDGES];
__device__ float g_Wt[EMB * EMB];   // g_Wt[i*64+d] = w[d*64+i]; 16KB, L1-resident

// Per-edge triplet run boundaries (id_reduce sorted, runs contiguous; Kidx
// within each run is 0..count-1, so stage 1 is a dense contiguous GEMM).
// Also transposes the weight so main-kernel W loads are d-contiguous.
__global__ void prep_kernel(const int* __restrict__ id_reduce,
                            const int* __restrict__ Kidx,
                            const float* __restrict__ w, int nT)
{
    int t = blockIdx.x * blockDim.x + threadIdx.x;
    if (t < EMB * EMB) {
        int d = t >> 6, i = t & 63;
        g_Wt[i * EMB + d] = w[t];
    }
    if (t < nT) {
        int e = id_reduce[t];
        if (t == 0 || id_reduce[t - 1] != e) g_start[e] = t;
        if (t == nT - 1 || id_reduce[t + 1] != e) g_count[e] = Kidx[t] + 1;
    }
}

// ---- packed f32x2 helpers ----
__device__ __forceinline__ u64 pack2(float x) {
    u64 r; asm("mov.b64 %0, {%1, %1};" : "=l"(r) : "f"(x)); return r;
}
__device__ __forceinline__ u64 ffma2(u64 a, u64 b, u64 c) {
    u64 d; asm("fma.rn.f32x2 %0, %1, %2, %3;" : "=l"(d) : "l"(a), "l"(b), "l"(c)); return d;
}
__device__ __forceinline__ u64 fmul2(u64 a, u64 b) {
    u64 d; asm("mul.rn.f32x2 %0, %1, %2;" : "=l"(d) : "l"(a), "l"(b)); return d;
}
__device__ __forceinline__ u64 fadd2(u64 a, u64 b) {
    u64 d; asm("add.rn.f32x2 %0, %1, %2;" : "=l"(d) : "l"(a), "l"(b)); return d;
}

// One warp per edge PAIR. Lane layout: db = lane&7 (d in [8db,8db+8) as 4
// f32x2), sb = lane>>3 (s in [4sb,4sb+4)). All operands stream through LDG
// (L1 dedups by cache line; no shared memory in this kernel at all).
__global__ void __launch_bounds__(128, 3)
main_kernel(const float* __restrict__ rbf,
            const float* __restrict__ sph,
            const float* __restrict__ m,
            float* __restrict__ out, int nEdges)
{
    const int tid  = threadIdx.x;
    const int lane = tid & 31;
    const int db   = lane & 7;
    const int sb   = lane >> 3;

    const int gwarp  = blockIdx.x * 4 + (tid >> 5);
    const int nwarps = gridDim.x * 4;
    const int npairs = (nEdges + 1) >> 1;

    for (int p = gwarp; p < npairs; p += nwarps) {
        const int e0 = 2 * p;
        const int e1 = (2 * p + 1 < nEdges) ? 2 * p + 1 : e0;

        // ---- stage 2: B[e][d][s] = sum_i Wt[i][d] * rbf[e][i][s] ----
        u64 accB0[4][4], accB1[4][4];   // [dp][s]
        #pragma unroll
        for (int dp = 0; dp < 4; dp++)
            #pragma unroll
            for (int s = 0; s < 4; s++) { accB0[dp][s] = 0ull; accB1[dp][s] = 0ull; }

        const float4* rbf0 = (const float4*)(rbf + (size_t)e0 * (EMB * NSPH) + sb * 4);
        const float4* rbf1 = (const float4*)(rbf + (size_t)e1 * (EMB * NSPH) + sb * 4);
        const float4* wbase = (const float4*)(g_Wt + db * 8);

        #pragma unroll 8
        for (int k = 0; k < EMB; k++) {
            float4 wa = __ldg(wbase + k * 16 + 0);
            float4 wb = __ldg(wbase + k * 16 + 1);
            u64 w2[4];
            w2[0] = ((const u64*)&wa)[0];
            w2[1] = ((const u64*)&wa)[1];
            w2[2] = ((const u64*)&wb)[0];
            w2[3] = ((const u64*)&wb)[1];

            float4 r0 = __ldg(rbf0 + k * 4);
            float4 r1 = __ldg(rbf1 + k * 4);
            u64 rd0[4] = { pack2(r0.x), pack2(r0.y), pack2(r0.z), pack2(r0.w) };
            u64 rd1[4] = { pack2(r1.x), pack2(r1.y), pack2(r1.z), pack2(r1.w) };

            #pragma unroll
            for (int dp = 0; dp < 4; dp++)
                #pragma unroll
                for (int s = 0; s < 4; s++) {
                    accB0[dp][s] = ffma2(w2[dp], rd0[s], accB0[dp][s]);
                    accB1[dp][s] = ffma2(w2[dp], rd1[s], accB1[dp][s]);
                }
        }

        // ---- stage 1 + Hadamard per edge ----
        #pragma unroll 1
        for (int ei = 0; ei < 2; ei++) {
            const int e = ei ? e1 : e0;
            if (ei && e1 == e0) break;

            const int start = g_start[e];
            const int count = g_count[e];

            const float* sph_e = sph + (size_t)e * (NSPH * KMAX);
            const float* s0p = sph_e + (4 * sb + 0) * KMAX;
            const float* s1p = sph_e + (4 * sb + 1) * KMAX;
            const float* s2p = sph_e + (4 * sb + 2) * KMAX;
            const float* s3p = sph_e + (4 * sb + 3) * KMAX;

            u64 accA[4][4];   // [s][dp]
            #pragma unroll
            for (int s = 0; s < 4; s++)
                #pragma unroll
                for (int dp = 0; dp < 4; dp++) accA[s][dp] = 0ull;

            const float4* m_base = (const float4*)(m + (size_t)start * EMB + db * 8);

            const int t4 = count & ~3;
            for (int t0 = 0; t0 < t4; t0 += 4) {
                float4 sp0 = *(const float4*)(s0p + t0);
                float4 sp1 = *(const float4*)(s1p + t0);
                float4 sp2 = *(const float4*)(s2p + t0);
                float4 sp3 = *(const float4*)(s3p + t0);
                #pragma unroll
                for (int j = 0; j < 4; j++) {
                    float4 ma = m_base[(t0 + j) * 16 + 0];
                    float4 mb = m_base[(t0 + j) * 16 + 1];
                    u64 m2[4];
                    m2[0] = ((const u64*)&ma)[0];
                    m2[1] = ((const u64*)&ma)[1];
                    m2[2] = ((const u64*)&mb)[0];
                    m2[3] = ((const u64*)&mb)[1];
                    u64 sv[4] = { pack2(((const float*)&sp0)[j]),
                                  pack2(((const float*)&sp1)[j]),
                                  pack2(((const float*)&sp2)[j]),
                                  pack2(((const float*)&sp3)[j]) };
                    #pragma unroll
                    for (int s = 0; s < 4; s++)
                        #pragma unroll
                        for (int dp = 0; dp < 4; dp++)
                            accA[s][dp] = ffma2(sv[s], m2[dp], accA[s][dp]);
                }
            }
            for (int t = t4; t < count; t++) {
                float4 ma = m_base[t * 16 + 0];
                float4 mb = m_base[t * 16 + 1];
                u64 m2[4];
                m2[0] = ((const u64*)&ma)[0];
                m2[1] = ((const u64*)&ma)[1];
                m2[2] = ((const u64*)&mb)[0];
                m2[3] = ((const u64*)&mb)[1];
                u64 sv[4] = { pack2(s0p[t]), pack2(s1p[t]),
                              pack2(s2p[t]), pack2(s3p[t]) };
                #pragma unroll
                for (int s = 0; s < 4; s++)
                    #pragma unroll
                    for (int dp = 0; dp < 4; dp++)
                        accA[s][dp] = ffma2(sv[s], m2[dp], accA[s][dp]);
            }

            // Hadamard + s-reduction
            u64 osum[4];
            #pragma unroll
            for (int dp = 0; dp < 4; dp++) {
                u64 b0 = ei ? accB1[dp][0] : accB0[dp][0];
                u64 b1 = ei ? accB1[dp][1] : accB0[dp][1];
                u64 b2 = ei ? accB1[dp][2] : accB0[dp][2];
                u64 b3 = ei ? accB1[dp][3] : accB0[dp][3];
                u64 acc = fmul2(b0, accA[0][dp]);
                acc = ffma2(b1, accA[1][dp], acc);
                acc = ffma2(b2, accA[2][dp], acc);
                acc = ffma2(b3, accA[3][dp], acc);
                osum[dp] = acc;
            }
            #pragma unroll
            for (int off = 8; off <= 16; off <<= 1)
                #pragma unroll
                for (int dp = 0; dp < 4; dp++)
                    osum[dp] = fadd2(osum[dp],
                                     __shfl_xor_sync(0xffffffffu, osum[dp], off));

            if (sb == 0) {
                float4 o0, o1;
                ((u64*)&o0)[0] = osum[0];
                ((u64*)&o0)[1] = osum[1];
                ((u64*)&o1)[0] = osum[2];
                ((u64*)&o1)[1] = osum[3];
                float4* op = (float4*)(out + (size_t)e * EMB + db * 8);
                op[0] = o0;
                op[1] = o1;
            }
        }
    }
}

extern "C" void kernel_launch(void* const* d_in, const int* in_sizes, int n_in,
                              void* d_out, int out_size)
{
    const float* rbf  = (const float*)d_in[0];
    const float* sph  = (const float*)d_in[1];
    const float* m    = (const float*)d_in[2];
    const float* w    = (const float*)d_in[3];
    const int*   idr  = (const int*)d_in[4];
    const int*   kidx = (const int*)d_in[5];

    const int nEdges = in_sizes[0] / (EMB * NSPH);
    const int nT     = in_sizes[4];

    prep_kernel<<<(nT + 255) / 256, 256>>>(idr, kidx, w, nT);
    main_kernel<<<NBLOCKS, 128>>>(rbf, sph, m, (float*)d_out, nEdges);
}